// round 16
// baseline (speedup 1.0000x reference)
#include <cuda_runtime.h>
#include <math.h>
#include <stdint.h>

#define BATCH   64
#define TSTEPS  256
#define EMB     512
#define HID     1024
#define GATES   4096
#define NBLK    128            // persistent CTAs (1 per SM, <=148)
#define KKP     260            // padded h-chunk row stride (floats)
#define KKP4    (KKP/4)        // 65 float4
#define SMEM_REC ((32*1024 + 64*KKP) * 4)   // 197632 bytes

// ---------------- device scratch (no runtime alloc) ----------------
__device__ __align__(16) float g_G   [(size_t)BATCH * TSTEPS * GATES]; // 268 MB
__device__ __align__(16) float g_Hall[(size_t)BATCH * TSTEPS * HID];   // 67 MB, rows (t*64+b)
__device__ __align__(16) float g_h   [BATCH * HID];                    // current h, [b][k]
__device__ __align__(16) float g_gatesT[GATES * BATCH];                // [c][b]
__device__ unsigned g_tk;   // barrier ticket counter (monotonic per launch)
__device__ unsigned g_gen;  // completed barrier phases

// ---------------- helpers ----------------
__device__ __forceinline__ float sigf(float x) { return 1.0f / (1.0f + expf(-x)); }

// Monotonic ticket grid barrier: no reset race between consecutive barriers.
__device__ __forceinline__ void gbar() {
    __syncthreads();
    if (threadIdx.x == 0) {
        __threadfence();
        unsigned tkt   = atomicAdd(&g_tk, 1u);
        unsigned phase = tkt >> 7;                 // /NBLK
        if ((tkt & (NBLK - 1u)) == NBLK - 1u) {
            atomicAdd(&g_gen, 1u);                 // release phase
        } else {
            while (*(volatile unsigned*)&g_gen <= phase) { __nanosleep(64); }
        }
        __threadfence();
    }
    __syncthreads();
}

// ---------------- init: zero h and barrier counters ----------------
__global__ void init_kernel() {
    int i = blockIdx.x * blockDim.x + threadIdx.x;       // 64*256 = 16384 float4
    ((float4*)g_h)[i] = make_float4(0.f, 0.f, 0.f, 0.f);
    if (i == 0) { g_tk = 0u; g_gen = 0u; }
}

// ---------------- generic NT GEMM: C[M,N] = A[M,K] @ B[N,K]^T + bias ----------------
// 128x128 block tile, K-chunk 16, 256 threads, 8x8 microtile, reg-double-buffered loads.
// remap!=0: output row m = t*64+b is written to row (b*256+t) (phase-3 time->batch remap).
__global__ void __launch_bounds__(256) gemm_nt(
    const float* __restrict__ A, const float* __restrict__ Bm, float* __restrict__ C,
    int K, int N,
    const float* __restrict__ bias1, const float* __restrict__ bias2, int remap)
{
    __shared__ float As[16][132];
    __shared__ float Bs[16][132];
    const int tid = threadIdx.x;
    const int m0 = blockIdx.y * 128;
    const int n0 = blockIdx.x * 128;
    const int tx = tid & 15;          // n-tile
    const int ty = tid >> 4;          // m-tile
    const int lrow = tid >> 1;        // 0..127 (loader row)
    const int lk   = (tid & 1) * 8;   // loader k offset (covers k..k+7)

    const float4* A4 = (const float4*)(A + (size_t)(m0 + lrow) * K);
    const float4* B4 = (const float4*)(Bm + (size_t)(n0 + lrow) * K);

    float acc[8][8];
#pragma unroll
    for (int i = 0; i < 8; i++)
#pragma unroll
        for (int j = 0; j < 8; j++) acc[i][j] = 0.f;

    const int nk = K >> 4;
    float4 a0 = A4[lk >> 2], a1 = A4[(lk >> 2) + 1];
    float4 b0 = B4[lk >> 2], b1 = B4[(lk >> 2) + 1];

    for (int kt = 0; kt < nk; kt++) {
        As[lk + 0][lrow] = a0.x; As[lk + 1][lrow] = a0.y;
        As[lk + 2][lrow] = a0.z; As[lk + 3][lrow] = a0.w;
        As[lk + 4][lrow] = a1.x; As[lk + 5][lrow] = a1.y;
        As[lk + 6][lrow] = a1.z; As[lk + 7][lrow] = a1.w;
        Bs[lk + 0][lrow] = b0.x; Bs[lk + 1][lrow] = b0.y;
        Bs[lk + 2][lrow] = b0.z; Bs[lk + 3][lrow] = b0.w;
        Bs[lk + 4][lrow] = b1.x; Bs[lk + 5][lrow] = b1.y;
        Bs[lk + 6][lrow] = b1.z; Bs[lk + 7][lrow] = b1.w;
        __syncthreads();

        if (kt + 1 < nk) {
            int ko = ((kt + 1) * 16 + lk) >> 2;
            a0 = A4[ko]; a1 = A4[ko + 1];
            b0 = B4[ko]; b1 = B4[ko + 1];
        }

#pragma unroll
        for (int kk = 0; kk < 16; kk++) {
            float af[8], bf[8];
            *(float4*)&af[0] = *(const float4*)&As[kk][ty * 8];
            *(float4*)&af[4] = *(const float4*)&As[kk][ty * 8 + 4];
            *(float4*)&bf[0] = *(const float4*)&Bs[kk][tx * 8];
            *(float4*)&bf[4] = *(const float4*)&Bs[kk][tx * 8 + 4];
#pragma unroll
            for (int i = 0; i < 8; i++)
#pragma unroll
                for (int j = 0; j < 8; j++)
                    acc[i][j] += af[i] * bf[j];
        }
        __syncthreads();
    }

    float bsum[8];
#pragma unroll
    for (int j = 0; j < 8; j++) {
        int n = n0 + tx * 8 + j;
        float bv = bias1 ? bias1[n] : 0.f;
        if (bias2) bv += bias2[n];
        bsum[j] = bv;
    }

#pragma unroll
    for (int i = 0; i < 8; i++) {
        int m = m0 + ty * 8 + i;
        int row = m;
        if (remap) {                       // m = t*64+b -> row = b*256+t
            int t = m >> 6, b = m & 63;
            row = b * TSTEPS + t;
        }
        float* Crow = C + (size_t)row * N + n0 + tx * 8;
        float4 v0, v1;
        v0.x = acc[i][0] + bsum[0]; v0.y = acc[i][1] + bsum[1];
        v0.z = acc[i][2] + bsum[2]; v0.w = acc[i][3] + bsum[3];
        v1.x = acc[i][4] + bsum[4]; v1.y = acc[i][5] + bsum[5];
        v1.z = acc[i][6] + bsum[6]; v1.w = acc[i][7] + bsum[7];
        *(float4*)&Crow[0] = v0;
        *(float4*)&Crow[4] = v1;
    }
}

// ---------------- persistent recurrent LSTM kernel ----------------
// 128 CTAs x 256 threads. Each CTA: 32 gate columns (GEMV role) + 8 h columns (update role).
// W_hh slice (32x1024 f32 = 128 KB) resident in SMEM for all 256 steps.
__global__ void __launch_bounds__(256) lstm_rec(const float* __restrict__ Whh)
{
    extern __shared__ float sm[];
    float* Ws = sm;                     // [32][1024]
    float* hs = sm + 32 * 1024;         // [64][KKP] chunk of h
    float4* Ws4 = (float4*)Ws;
    float4* hs4 = (float4*)hs;

    const int tid = threadIdx.x;
    const int cta = blockIdx.x;
    const int b   = tid & 63;           // batch row (both roles)
    const int cg  = tid >> 6;           // 0..3 column group (GEMV role)
    const int colbase = cta * 32;
    const int j0  = cta * 8;            // h-column base (update role)
    const int jA  = tid >> 6;           // update j: jA and jA+4

    // Load W_hh slice into SMEM (once).
    {
        const float4* W4 = (const float4*)(Whh + (size_t)colbase * HID);
#pragma unroll
        for (int i = 0; i < 32; i++) {
            int f = i * 256 + tid;      // 8192 float4
            Ws4[f] = W4[f];
        }
    }
    float cst0 = 0.f, cst1 = 0.f;       // cell state lives in registers all 256 steps
    __syncthreads();

    const float4* gh4 = (const float4*)g_h;
    const float*  Gb  = g_G + (size_t)b * TSTEPS * GATES;

    for (int t = 0; t < TSTEPS; t++) {
        // Prefetch G (x-part + biases) for this thread's update work.
        const float* Gt = Gb + (size_t)t * GATES;
        const int cA = j0 + jA;
        const int cB = cA + 4;
        float Gp0 = __ldg(Gt + cA);
        float Gp1 = __ldg(Gt + 1024 + cA);
        float Gp2 = __ldg(Gt + 2048 + cA);
        float Gp3 = __ldg(Gt + 3072 + cA);
        float Gp4 = __ldg(Gt + cB);
        float Gp5 = __ldg(Gt + 1024 + cB);
        float Gp6 = __ldg(Gt + 2048 + cB);
        float Gp7 = __ldg(Gt + 3072 + cB);

        // GEMV: acc[j] = h . Whh[colbase+cg*8+j]
        float acc[8] = {0.f, 0.f, 0.f, 0.f, 0.f, 0.f, 0.f, 0.f};
        for (int kc = 0; kc < 4; kc++) {
            // Cooperative load of h chunk [64 x 256] (cross-SM -> __ldcg).
#pragma unroll
            for (int i = 0; i < 16; i++) {
                int f  = i * 256 + tid;     // 4096 float4
                int bb = f >> 6;
                int kf = f & 63;
                hs4[bb * KKP4 + kf] = __ldcg(gh4 + bb * 256 + kc * 64 + kf);
            }
            __syncthreads();
            const float4* hb = hs4 + b * KKP4;
            const float4* wb = Ws4 + (cg * 8) * 256 + kc * 64;
#pragma unroll 8
            for (int kk = 0; kk < 64; kk++) {
                float4 hv = hb[kk];
#pragma unroll
                for (int j = 0; j < 8; j++) {
                    float4 wv = wb[j * 256 + kk];
                    acc[j] += hv.x * wv.x;
                    acc[j] += hv.y * wv.y;
                    acc[j] += hv.z * wv.z;
                    acc[j] += hv.w * wv.w;
                }
            }
            __syncthreads();
        }
        // Publish gate partials, transposed [c][b] for coalesced access.
#pragma unroll
        for (int j = 0; j < 8; j++)
            g_gatesT[(colbase + cg * 8 + j) * 64 + b] = acc[j];

        gbar();   // all gates visible

        // Update role: (b, cA) and (b, cB).
        {
            float ig = __ldcg(&g_gatesT[cA * 64 + b]) + Gp0;
            float fg = __ldcg(&g_gatesT[(1024 + cA) * 64 + b]) + Gp1;
            float gg = __ldcg(&g_gatesT[(2048 + cA) * 64 + b]) + Gp2;
            float og = __ldcg(&g_gatesT[(3072 + cA) * 64 + b]) + Gp3;
            cst0 = sigf(fg) * cst0 + sigf(ig) * tanhf(gg);
            float h = sigf(og) * tanhf(cst0);
            g_h[b * HID + cA] = h;
            g_Hall[((size_t)t * 64 + b) * HID + cA] = h;
        }
        {
            float ig = __ldcg(&g_gatesT[cB * 64 + b]) + Gp4;
            float fg = __ldcg(&g_gatesT[(1024 + cB) * 64 + b]) + Gp5;
            float gg = __ldcg(&g_gatesT[(2048 + cB) * 64 + b]) + Gp6;
            float og = __ldcg(&g_gatesT[(3072 + cB) * 64 + b]) + Gp7;
            cst1 = sigf(fg) * cst1 + sigf(ig) * tanhf(gg);
            float h = sigf(og) * tanhf(cst1);
            g_h[b * HID + cB] = h;
            g_Hall[((size_t)t * 64 + b) * HID + cB] = h;
        }

        gbar();   // h published for next step
    }
}

// ---------------- launch ----------------
extern "C" void kernel_launch(void* const* d_in, const int* in_sizes, int n_in,
                              void* d_out, int out_size) {
    (void)in_sizes; (void)n_in; (void)out_size;
    const float* emb  = (const float*)d_in[0];  // [64,256,512]
    const float* W_ih = (const float*)d_in[1];  // [4096,512]
    const float* W_hh = (const float*)d_in[2];  // [4096,1024]
    const float* b_ih = (const float*)d_in[3];  // [4096]
    const float* b_hh = (const float*)d_in[4];  // [4096]
    const float* W_fc = (const float*)d_in[5];  // [1024,1024]
    const float* b_fc = (const float*)d_in[6];  // [1024]
    float* out = (float*)d_out;                 // [64,256,1024]

    void *pG = nullptr, *pHall = nullptr;
    cudaGetSymbolAddress(&pG, g_G);
    cudaGetSymbolAddress(&pHall, g_Hall);

    cudaFuncSetAttribute(lstm_rec, cudaFuncAttributeMaxDynamicSharedMemorySize, SMEM_REC);

    // 0) zero h + barrier counters (re-zeroed each replay)
    init_kernel<<<64, 256>>>();

    // 1) G = emb @ W_ih^T + b_ih + b_hh   (M=16384, N=4096, K=512)
    gemm_nt<<<dim3(GATES / 128, (BATCH * TSTEPS) / 128), 256>>>(
        emb, W_ih, (float*)pG, EMB, GATES, b_ih, b_hh, 0);

    // 2) recurrent sweep (persistent, grid-barriered)
    lstm_rec<<<NBLK, 256, SMEM_REC>>>(W_hh);

    // 3) out[b,t,:] = Hall[t*64+b,:] @ W_fc^T + b_fc  (M=16384, N=1024, K=1024, remap)
    gemm_nt<<<dim3(HID / 128, (BATCH * TSTEPS) / 128), 256>>>(
        (const float*)pHall, W_fc, out, HID, HID, b_fc, nullptr, 1);
}

// round 17
// speedup vs baseline: 1.2480x; 1.2480x over previous
#include <cuda_runtime.h>
#include <math.h>
#include <stdint.h>

#define BATCH   64
#define TSTEPS  256
#define EMB     512
#define HID     1024
#define GATES   4096
#define NBLK    128
#define THREADS 256

// Wq: 256 k4-rows x 33 float4 (8 j x 4 g + 1 pad f4)  -> bank-spread
#define WQ_F4    (256 * 33)          // 8448 float4
#define HSBUF_F4 (16 * 65)           // 1040 float4 per h buffer (16 bg x 65)
#define SMEM_REC ((WQ_F4 + 4 * HSBUF_F4) * 16)   // 201728 bytes

// ---------------- device scratch ----------------
__device__ __align__(16) float g_G   [(size_t)BATCH * TSTEPS * GATES]; // 256 MB
__device__ __align__(16) float g_Hall[(size_t)BATCH * TSTEPS * HID];   // 64 MB, rows (t*64+b)
__device__ __align__(16) float g_h2  [2 * BATCH * HID];                // double-buffered h
__device__ unsigned g_tk;   // barrier ticket counter
__device__ unsigned g_gen;  // completed barrier phases

__device__ __forceinline__ float sigf(float x)  { return 1.0f / (1.0f + __expf(-x)); }
__device__ __forceinline__ float tanhf_(float x){ return 1.0f - 2.0f / (__expf(2.0f * x) + 1.0f); }

// Monotonic ticket grid barrier (no reset race).
__device__ __forceinline__ void gbar() {
    __syncthreads();
    if (threadIdx.x == 0) {
        __threadfence();
        unsigned tkt   = atomicAdd(&g_tk, 1u);
        unsigned phase = tkt >> 7;                 // /NBLK
        if ((tkt & (NBLK - 1u)) == NBLK - 1u) {
            atomicAdd(&g_gen, 1u);
        } else {
            while (*(volatile unsigned*)&g_gen <= phase) { __nanosleep(32); }
        }
        __threadfence();
    }
    __syncthreads();
}

__global__ void init_kernel() {
    int i = blockIdx.x * blockDim.x + threadIdx.x;       // 64*256 = 16384 float4
    ((float4*)g_h2)[i] = make_float4(0.f, 0.f, 0.f, 0.f); // zero buffer 0 (h_0)
    if (i == 0) { g_tk = 0u; g_gen = 0u; }
}

// ---------------- generic NT GEMM (unchanged, known-good) ----------------
__global__ void __launch_bounds__(256) gemm_nt(
    const float* __restrict__ A, const float* __restrict__ Bm, float* __restrict__ C,
    int K, int N,
    const float* __restrict__ bias1, const float* __restrict__ bias2, int remap)
{
    __shared__ float As[16][132];
    __shared__ float Bs[16][132];
    const int tid = threadIdx.x;
    const int m0 = blockIdx.y * 128;
    const int n0 = blockIdx.x * 128;
    const int tx = tid & 15;
    const int ty = tid >> 4;
    const int lrow = tid >> 1;
    const int lk   = (tid & 1) * 8;

    const float4* A4 = (const float4*)(A + (size_t)(m0 + lrow) * K);
    const float4* B4 = (const float4*)(Bm + (size_t)(n0 + lrow) * K);

    float acc[8][8];
#pragma unroll
    for (int i = 0; i < 8; i++)
#pragma unroll
        for (int j = 0; j < 8; j++) acc[i][j] = 0.f;

    const int nk = K >> 4;
    float4 a0 = A4[lk >> 2], a1 = A4[(lk >> 2) + 1];
    float4 b0 = B4[lk >> 2], b1 = B4[(lk >> 2) + 1];

    for (int kt = 0; kt < nk; kt++) {
        As[lk + 0][lrow] = a0.x; As[lk + 1][lrow] = a0.y;
        As[lk + 2][lrow] = a0.z; As[lk + 3][lrow] = a0.w;
        As[lk + 4][lrow] = a1.x; As[lk + 5][lrow] = a1.y;
        As[lk + 6][lrow] = a1.z; As[lk + 7][lrow] = a1.w;
        Bs[lk + 0][lrow] = b0.x; Bs[lk + 1][lrow] = b0.y;
        Bs[lk + 2][lrow] = b0.z; Bs[lk + 3][lrow] = b0.w;
        Bs[lk + 4][lrow] = b1.x; Bs[lk + 5][lrow] = b1.y;
        Bs[lk + 6][lrow] = b1.z; Bs[lk + 7][lrow] = b1.w;
        __syncthreads();

        if (kt + 1 < nk) {
            int ko = ((kt + 1) * 16 + lk) >> 2;
            a0 = A4[ko]; a1 = A4[ko + 1];
            b0 = B4[ko]; b1 = B4[ko + 1];
        }

#pragma unroll
        for (int kk = 0; kk < 16; kk++) {
            float af[8], bf[8];
            *(float4*)&af[0] = *(const float4*)&As[kk][ty * 8];
            *(float4*)&af[4] = *(const float4*)&As[kk][ty * 8 + 4];
            *(float4*)&bf[0] = *(const float4*)&Bs[kk][tx * 8];
            *(float4*)&bf[4] = *(const float4*)&Bs[kk][tx * 8 + 4];
#pragma unroll
            for (int i = 0; i < 8; i++)
#pragma unroll
                for (int j = 0; j < 8; j++)
                    acc[i][j] += af[i] * bf[j];
        }
        __syncthreads();
    }

    float bsum[8];
#pragma unroll
    for (int j = 0; j < 8; j++) {
        int n = n0 + tx * 8 + j;
        float bv = bias1 ? bias1[n] : 0.f;
        if (bias2) bv += bias2[n];
        bsum[j] = bv;
    }

#pragma unroll
    for (int i = 0; i < 8; i++) {
        int m = m0 + ty * 8 + i;
        int row = m;
        if (remap) {                       // m = t*64+b -> row = b*256+t
            int t = m >> 6, b = m & 63;
            row = b * TSTEPS + t;
        }
        float* Crow = C + (size_t)row * N + n0 + tx * 8;
        float4 v0, v1;
        v0.x = acc[i][0] + bsum[0]; v0.y = acc[i][1] + bsum[1];
        v0.z = acc[i][2] + bsum[2]; v0.w = acc[i][3] + bsum[3];
        v1.x = acc[i][4] + bsum[4]; v1.y = acc[i][5] + bsum[5];
        v1.z = acc[i][6] + bsum[6]; v1.w = acc[i][7] + bsum[7];
        *(float4*)&Crow[0] = v0;
        *(float4*)&Crow[4] = v1;
    }
}

// ---------------- persistent recurrent LSTM (v2) ----------------
// 128 CTAs x 256 threads. CTA c owns h-cols [8c,8c+8), all 4 gates.
// Thread: half = tid>>7 (k range), j = (tid>>4)&7 (h-col), bg = tid&15 (4 batches).
// 16 accumulators/thread = 4 gates x 4 batches. Cell state in registers.
#define DOT4(gi, wv, hv, bi)                                        \
    acc[(gi)*4+(bi)] += (wv).x * (hv).x;                            \
    acc[(gi)*4+(bi)] += (wv).y * (hv).y;                            \
    acc[(gi)*4+(bi)] += (wv).z * (hv).z;                            \
    acc[(gi)*4+(bi)] += (wv).w * (hv).w;

__global__ void __launch_bounds__(THREADS, 1) lstm_rec(const float* __restrict__ Whh)
{
    extern __shared__ float sm[];
    float4* Wq4 = (float4*)sm;
    float4* Hs4 = (float4*)sm + WQ_F4;      // 4 buffers (half*2+buf) x 1040 f4
    float*  red = (float*)Hs4;              // reduction buffer (reuses half0/buf0)

    const int tid  = threadIdx.x;
    const int cta  = blockIdx.x;
    const int half = tid >> 7;
    const int j    = (tid >> 4) & 7;
    const int bg   = tid & 15;
    const int lane = tid & 31;
    const int wh   = (tid >> 5) & 3;        // warp within half
    const int bg_s = lane >> 1;             // staging role
    const int kp   = lane & 1;

    // Load W_hh slice into Wq layout: Wq4[k4*33 + j*4 + g] = W[g*1024+8c+j][4k4..4k4+3]
    for (int m = tid; m < 8192; m += THREADS) {
        int k4 = m & 255, jj = (m >> 8) & 7, g = m >> 11;
        int row = g * HID + cta * 8 + jj;
        float4 v = __ldg((const float4*)Whh + (size_t)row * 256 + k4);
        Wq4[k4 * 33 + jj * 4 + g] = v;
    }
    __syncthreads();

    float cst[4] = {0.f, 0.f, 0.f, 0.f};

    for (int t = 0; t < TSTEPS; t++) {
        // G prefetch (half-0 updates)
        float Gp[16];
        if (half == 0) {
#pragma unroll
            for (int g = 0; g < 4; g++)
#pragma unroll
                for (int bi = 0; bi < 4; bi++) {
                    int b = 4 * bg + bi;
                    Gp[g * 4 + bi] =
                        __ldg(&g_G[((size_t)b * TSTEPS + t) * GATES + g * HID + cta * 8 + j]);
                }
        } else {
#pragma unroll
            for (int i = 0; i < 16; i++) Gp[i] = 0.f;
        }

        const float4* hsrc = (const float4*)g_h2 + (size_t)(t & 1) * (BATCH * HID / 4);

        // issue chunk 0 (cp.async, .cg = L2 path, cross-SM coherent)
        {
            uint32_t dbase = (uint32_t)__cvta_generic_to_shared(Hs4 + (half * 2 + 0) * HSBUF_F4);
#pragma unroll
            for (int it = 0; it < 8; it++) {
                int gi = wh * 8 + it;
                int bi = gi & 3, kko = gi >> 2;
                int kk4 = kko * 2 + kp;
                int b = 4 * bg_s + bi;
                const float4* src = hsrc + b * 256 + half * 128 + kk4;
                uint32_t dst = dbase + (uint32_t)(bg_s * 65 + kk4 * 4 + bi) * 16;
                asm volatile("cp.async.cg.shared.global [%0], [%1], 16;\n"
                             :: "r"(dst), "l"(src) : "memory");
            }
            asm volatile("cp.async.commit_group;\n" ::: "memory");
        }

        float acc[16];
#pragma unroll
        for (int i = 0; i < 16; i++) acc[i] = 0.f;

        for (int kc = 0; kc < 8; kc++) {
            if (kc < 7) {
                int buf = (kc + 1) & 1;
                uint32_t dbase =
                    (uint32_t)__cvta_generic_to_shared(Hs4 + (half * 2 + buf) * HSBUF_F4);
#pragma unroll
                for (int it = 0; it < 8; it++) {
                    int gi = wh * 8 + it;
                    int bi = gi & 3, kko = gi >> 2;
                    int kk4 = kko * 2 + kp;
                    int b = 4 * bg_s + bi;
                    const float4* src = hsrc + b * 256 + half * 128 + (kc + 1) * 16 + kk4;
                    uint32_t dst = dbase + (uint32_t)(bg_s * 65 + kk4 * 4 + bi) * 16;
                    asm volatile("cp.async.cg.shared.global [%0], [%1], 16;\n"
                                 :: "r"(dst), "l"(src) : "memory");
                }
                asm volatile("cp.async.commit_group;\n" ::: "memory");
                asm volatile("cp.async.wait_group 1;\n" ::: "memory");
            } else {
                asm volatile("cp.async.wait_group 0;\n" ::: "memory");
            }
            __syncthreads();

            const float4* hb = Hs4 + (half * 2 + (kc & 1)) * HSBUF_F4 + bg * 65;
            const float4* wb = Wq4 + (size_t)(half * 128 + kc * 16) * 33 + j * 4;
#pragma unroll 4
            for (int kk4 = 0; kk4 < 16; kk4++) {
                float4 w0 = wb[kk4 * 33 + 0];
                float4 w1 = wb[kk4 * 33 + 1];
                float4 w2 = wb[kk4 * 33 + 2];
                float4 w3 = wb[kk4 * 33 + 3];
                float4 h0 = hb[kk4 * 4 + 0];
                float4 h1 = hb[kk4 * 4 + 1];
                float4 h2 = hb[kk4 * 4 + 2];
                float4 h3 = hb[kk4 * 4 + 3];
                DOT4(0, w0, h0, 0) DOT4(0, w0, h1, 1) DOT4(0, w0, h2, 2) DOT4(0, w0, h3, 3)
                DOT4(1, w1, h0, 0) DOT4(1, w1, h1, 1) DOT4(1, w1, h2, 2) DOT4(1, w1, h3, 3)
                DOT4(2, w2, h0, 0) DOT4(2, w2, h1, 1) DOT4(2, w2, h2, 2) DOT4(2, w2, h3, 3)
                DOT4(3, w3, h0, 0) DOT4(3, w3, h1, 1) DOT4(3, w3, h2, 2) DOT4(3, w3, h3, 3)
            }
            __syncthreads();
        }

        // cross-half reduction (half1 -> smem -> half0)
        if (half == 1) {
            int lt = tid & 127;
#pragma unroll
            for (int i = 0; i < 16; i++) red[lt * 17 + i] = acc[i];
        }
        __syncthreads();

        if (half == 0) {
            const int col = cta * 8 + j;
            float* hdst = g_h2 + (size_t)((t + 1) & 1) * BATCH * HID;
#pragma unroll
            for (int bi = 0; bi < 4; bi++) {
                int b = 4 * bg + bi;
                float ai = acc[0 * 4 + bi] + red[tid * 17 + 0 * 4 + bi] + Gp[0 * 4 + bi];
                float af = acc[1 * 4 + bi] + red[tid * 17 + 1 * 4 + bi] + Gp[1 * 4 + bi];
                float ag = acc[2 * 4 + bi] + red[tid * 17 + 2 * 4 + bi] + Gp[2 * 4 + bi];
                float ao = acc[3 * 4 + bi] + red[tid * 17 + 3 * 4 + bi] + Gp[3 * 4 + bi];
                float c = sigf(af) * cst[bi] + sigf(ai) * tanhf_(ag);
                cst[bi] = c;
                float h = sigf(ao) * tanhf_(c);
                hdst[b * HID + col] = h;
                g_Hall[((size_t)t * BATCH + b) * HID + col] = h;
            }
        }

        gbar();   // h(t+1) published; next step stages from the other buffer
    }
}

// ---------------- launch ----------------
extern "C" void kernel_launch(void* const* d_in, const int* in_sizes, int n_in,
                              void* d_out, int out_size) {
    (void)in_sizes; (void)n_in; (void)out_size;
    const float* emb  = (const float*)d_in[0];  // [64,256,512]
    const float* W_ih = (const float*)d_in[1];  // [4096,512]
    const float* W_hh = (const float*)d_in[2];  // [4096,1024]
    const float* b_ih = (const float*)d_in[3];  // [4096]
    const float* b_hh = (const float*)d_in[4];  // [4096]
    const float* W_fc = (const float*)d_in[5];  // [1024,1024]
    const float* b_fc = (const float*)d_in[6];  // [1024]
    float* out = (float*)d_out;                 // [64,256,1024]

    void *pG = nullptr, *pHall = nullptr;
    cudaGetSymbolAddress(&pG, g_G);
    cudaGetSymbolAddress(&pHall, g_Hall);

    cudaFuncSetAttribute(lstm_rec, cudaFuncAttributeMaxDynamicSharedMemorySize, SMEM_REC);

    // 0) zero h buffer 0 + barrier counters (per replay)
    init_kernel<<<64, 256>>>();

    // 1) G = emb @ W_ih^T + b_ih + b_hh   (M=16384, N=4096, K=512)
    gemm_nt<<<dim3(GATES / 128, (BATCH * TSTEPS) / 128), 256>>>(
        emb, W_ih, (float*)pG, EMB, GATES, b_ih, b_hh, 0);

    // 2) recurrent sweep (persistent, 1 grid barrier/step)
    lstm_rec<<<NBLK, THREADS, SMEM_REC>>>(W_hh);

    // 3) out[b,t,:] = Hall[t*64+b,:] @ W_fc^T + b_fc
    gemm_nt<<<dim3(HID / 128, (BATCH * TSTEPS) / 128), 256>>>(
        (const float*)pHall, W_fc, out, HID, HID, b_fc, nullptr, 1);
}